// round 4
// baseline (speedup 1.0000x reference)
#include <cuda_runtime.h>
#include <cuda_bf16.h>
#include <math.h>
#include <stdint.h>

// Problem constants
#define BATCH 8
#define T_SEQ 1024
#define C_EMB 768
#define NH    8
#define HD    96
#define M_ROWS (BATCH * T_SEQ)   // 8192
#define GK    768                // GEMM K (both projections)

// ---------------------------------------------------------------------------
// Scratch
// ---------------------------------------------------------------------------
__device__ float g_qkv[(size_t)M_ROWS * 3 * C_EMB];
__device__ float g_att[(size_t)M_ROWS * C_EMB];

// ---------------------------------------------------------------------------
// mma.sync bf16 helper (baseline PTX, works at compute_103)
// D(f32) += A(bf16) * B(bf16): m16n8k16, A row-major, B col-major
// ---------------------------------------------------------------------------
__device__ __forceinline__ void mma_bf16(
    float& c0, float& c1, float& c2, float& c3,
    uint32_t a0, uint32_t a1, uint32_t a2, uint32_t a3,
    uint32_t b0, uint32_t b1)
{
    asm volatile(
        "mma.sync.aligned.m16n8k16.row.col.f32.bf16.bf16.f32 "
        "{%0,%1,%2,%3}, {%4,%5,%6,%7}, {%8,%9}, {%0,%1,%2,%3};"
        : "+f"(c0), "+f"(c1), "+f"(c2), "+f"(c3)
        : "r"(a0), "r"(a1), "r"(a2), "r"(a3), "r"(b0), "r"(b1));
}

__device__ __forceinline__ uint32_t pkbf(__nv_bfloat16 a, __nv_bfloat16 b) {
    __nv_bfloat162 t(a, b);
    return *reinterpret_cast<uint32_t*>(&t);
}

// ---------------------------------------------------------------------------
// Split-bf16 tensor-core GEMM:
//   C[m][n] = sum_k A[m][k] * W[n][k] + bias[n]
//   D = Ah*Bh + Ah*Bl + Al*Bh   (fp32 accumulate, rel err ~1e-5)
// CTA: 128 threads = 4 warps (1 x 4), CTA tile 64(m) x 128(n), warp 64x32.
// K chunked at 32, double-buffered smem, register-prefetch pipeline.
// Smem rows stride 40 bf16 => conflict-free LDS.32 fragment loads.
// ---------------------------------------------------------------------------
#define AS_STRIDE 40
#define ABUF (64 * AS_STRIDE)            // bf16 count per A split tile
#define BBUF (128 * AS_STRIDE)           // bf16 count per B split tile
#define BUFSZ (2 * ABUF + 2 * BBUF)      // Ah, Al, Bh, Bl
#define GEMM_SMEM_BYTES (2 * BUFSZ * 2)  // double buffer, bytes
#define NCHUNK (GK / 32)                 // 24

__global__ __launch_bounds__(128, 3) void gemm_mma(
    const float* __restrict__ A, const float* __restrict__ W,
    const float* __restrict__ bias, float* __restrict__ C, int N)
{
    extern __shared__ __nv_bfloat16 smb[];

    const int tid  = threadIdx.x;
    const int w    = tid >> 5;        // warp 0..3 -> n offset 32*w
    const int lane = tid & 31;
    const int gr   = lane >> 2;       // 0..7
    const int lc   = lane & 3;        // 0..3
    const int bm   = blockIdx.y * 64;
    const int bn   = blockIdx.x * 128;

    float acc[4][4][4];
#pragma unroll
    for (int mt = 0; mt < 4; mt++)
#pragma unroll
        for (int nt = 0; nt < 4; nt++)
#pragma unroll
            for (int r = 0; r < 4; r++) acc[mt][nt][r] = 0.f;

    // ---- fill chunk 0 into buffer 0 ----
    {
        __nv_bfloat16* Ah = smb;
        __nv_bfloat16* Al = Ah + ABUF;
        __nv_bfloat16* Bh = Al + ABUF;
        __nv_bfloat16* Bl = Bh + BBUF;
#pragma unroll
        for (int j = 0; j < 4; j++) {               // A: 64x32 fp32
            int i = tid + 128 * j;
            int r = i >> 3, c4 = (i & 7) * 4;
            float4 v = *(const float4*)(A + (size_t)(bm + r) * GK + c4);
            __nv_bfloat16 h0 = __float2bfloat16_rn(v.x), h1 = __float2bfloat16_rn(v.y);
            __nv_bfloat16 h2 = __float2bfloat16_rn(v.z), h3 = __float2bfloat16_rn(v.w);
            int idx = r * AS_STRIDE + c4;
            *(uint2*)&Ah[idx] = make_uint2(pkbf(h0, h1), pkbf(h2, h3));
            *(uint2*)&Al[idx] = make_uint2(
                pkbf(__float2bfloat16_rn(v.x - __bfloat162float(h0)),
                     __float2bfloat16_rn(v.y - __bfloat162float(h1))),
                pkbf(__float2bfloat16_rn(v.z - __bfloat162float(h2)),
                     __float2bfloat16_rn(v.w - __bfloat162float(h3))));
        }
#pragma unroll
        for (int j = 0; j < 8; j++) {               // B: 128x32 fp32
            int i = tid + 128 * j;
            int r = i >> 3, c4 = (i & 7) * 4;
            float4 v = *(const float4*)(W + (size_t)(bn + r) * GK + c4);
            __nv_bfloat16 h0 = __float2bfloat16_rn(v.x), h1 = __float2bfloat16_rn(v.y);
            __nv_bfloat16 h2 = __float2bfloat16_rn(v.z), h3 = __float2bfloat16_rn(v.w);
            int idx = r * AS_STRIDE + c4;
            *(uint2*)&Bh[idx] = make_uint2(pkbf(h0, h1), pkbf(h2, h3));
            *(uint2*)&Bl[idx] = make_uint2(
                pkbf(__float2bfloat16_rn(v.x - __bfloat162float(h0)),
                     __float2bfloat16_rn(v.y - __bfloat162float(h1))),
                pkbf(__float2bfloat16_rn(v.z - __bfloat162float(h2)),
                     __float2bfloat16_rn(v.w - __bfloat162float(h3))));
        }
    }
    __syncthreads();

    float4 pa[4], pb[8];
    for (int t = 0; t < NCHUNK; t++) {
        const bool more = (t + 1) < NCHUNK;
        if (more) {
            const int k0 = (t + 1) * 32;
#pragma unroll
            for (int j = 0; j < 4; j++) {
                int i = tid + 128 * j;
                int r = i >> 3, c4 = (i & 7) * 4;
                pa[j] = *(const float4*)(A + (size_t)(bm + r) * GK + k0 + c4);
            }
#pragma unroll
            for (int j = 0; j < 8; j++) {
                int i = tid + 128 * j;
                int r = i >> 3, c4 = (i & 7) * 4;
                pb[j] = *(const float4*)(W + (size_t)(bn + r) * GK + k0 + c4);
            }
        }

        // ---- MMA over current buffer ----
        {
            __nv_bfloat16* buf = smb + (t & 1) * BUFSZ;
            __nv_bfloat16* Ah = buf;
            __nv_bfloat16* Al = Ah + ABUF;
            __nv_bfloat16* Bh = Al + ABUF;
            __nv_bfloat16* Bl = Bh + BBUF;

#pragma unroll
            for (int ks = 0; ks < 2; ks++) {
                const int kb = ks * 16;
                uint32_t af[4][4], bhf[4][2], blf[4][2];
#pragma unroll
                for (int mt = 0; mt < 4; mt++) {
                    int r0 = (mt * 16 + gr) * AS_STRIDE + kb + lc * 2;
                    int r1 = r0 + 8 * AS_STRIDE;
                    af[mt][0] = *(const uint32_t*)&Ah[r0];
                    af[mt][1] = *(const uint32_t*)&Ah[r1];
                    af[mt][2] = *(const uint32_t*)&Ah[r0 + 8];
                    af[mt][3] = *(const uint32_t*)&Ah[r1 + 8];
                }
#pragma unroll
                for (int nt = 0; nt < 4; nt++) {
                    int rb = (w * 32 + nt * 8 + gr) * AS_STRIDE + kb + lc * 2;
                    bhf[nt][0] = *(const uint32_t*)&Bh[rb];
                    bhf[nt][1] = *(const uint32_t*)&Bh[rb + 8];
                    blf[nt][0] = *(const uint32_t*)&Bl[rb];
                    blf[nt][1] = *(const uint32_t*)&Bl[rb + 8];
                }
                // Ah*Bh and Ah*Bl
#pragma unroll
                for (int mt = 0; mt < 4; mt++)
#pragma unroll
                    for (int nt = 0; nt < 4; nt++) {
                        mma_bf16(acc[mt][nt][0], acc[mt][nt][1],
                                 acc[mt][nt][2], acc[mt][nt][3],
                                 af[mt][0], af[mt][1], af[mt][2], af[mt][3],
                                 bhf[nt][0], bhf[nt][1]);
                        mma_bf16(acc[mt][nt][0], acc[mt][nt][1],
                                 acc[mt][nt][2], acc[mt][nt][3],
                                 af[mt][0], af[mt][1], af[mt][2], af[mt][3],
                                 blf[nt][0], blf[nt][1]);
                    }
                // Al*Bh
#pragma unroll
                for (int mt = 0; mt < 4; mt++) {
                    int r0 = (mt * 16 + gr) * AS_STRIDE + kb + lc * 2;
                    int r1 = r0 + 8 * AS_STRIDE;
                    af[mt][0] = *(const uint32_t*)&Al[r0];
                    af[mt][1] = *(const uint32_t*)&Al[r1];
                    af[mt][2] = *(const uint32_t*)&Al[r0 + 8];
                    af[mt][3] = *(const uint32_t*)&Al[r1 + 8];
                }
#pragma unroll
                for (int mt = 0; mt < 4; mt++)
#pragma unroll
                    for (int nt = 0; nt < 4; nt++)
                        mma_bf16(acc[mt][nt][0], acc[mt][nt][1],
                                 acc[mt][nt][2], acc[mt][nt][3],
                                 af[mt][0], af[mt][1], af[mt][2], af[mt][3],
                                 bhf[nt][0], bhf[nt][1]);
            }
        }

        // ---- store prefetched chunk into other buffer ----
        if (more) {
            __nv_bfloat16* buf = smb + ((t + 1) & 1) * BUFSZ;
            __nv_bfloat16* Ah = buf;
            __nv_bfloat16* Al = Ah + ABUF;
            __nv_bfloat16* Bh = Al + ABUF;
            __nv_bfloat16* Bl = Bh + BBUF;
#pragma unroll
            for (int j = 0; j < 4; j++) {
                int i = tid + 128 * j;
                int r = i >> 3, c4 = (i & 7) * 4;
                float4 v = pa[j];
                __nv_bfloat16 h0 = __float2bfloat16_rn(v.x), h1 = __float2bfloat16_rn(v.y);
                __nv_bfloat16 h2 = __float2bfloat16_rn(v.z), h3 = __float2bfloat16_rn(v.w);
                int idx = r * AS_STRIDE + c4;
                *(uint2*)&Ah[idx] = make_uint2(pkbf(h0, h1), pkbf(h2, h3));
                *(uint2*)&Al[idx] = make_uint2(
                    pkbf(__float2bfloat16_rn(v.x - __bfloat162float(h0)),
                         __float2bfloat16_rn(v.y - __bfloat162float(h1))),
                    pkbf(__float2bfloat16_rn(v.z - __bfloat162float(h2)),
                         __float2bfloat16_rn(v.w - __bfloat162float(h3))));
            }
#pragma unroll
            for (int j = 0; j < 8; j++) {
                int i = tid + 128 * j;
                int r = i >> 3, c4 = (i & 7) * 4;
                float4 v = pb[j];
                __nv_bfloat16 h0 = __float2bfloat16_rn(v.x), h1 = __float2bfloat16_rn(v.y);
                __nv_bfloat16 h2 = __float2bfloat16_rn(v.z), h3 = __float2bfloat16_rn(v.w);
                int idx = r * AS_STRIDE + c4;
                *(uint2*)&Bh[idx] = make_uint2(pkbf(h0, h1), pkbf(h2, h3));
                *(uint2*)&Bl[idx] = make_uint2(
                    pkbf(__float2bfloat16_rn(v.x - __bfloat162float(h0)),
                         __float2bfloat16_rn(v.y - __bfloat162float(h1))),
                    pkbf(__float2bfloat16_rn(v.z - __bfloat162float(h2)),
                         __float2bfloat16_rn(v.w - __bfloat162float(h3))));
            }
        }
        __syncthreads();
    }

    // ---- epilogue: add bias, store ----
#pragma unroll
    for (int nt = 0; nt < 4; nt++) {
        const int col = bn + w * 32 + nt * 8 + lc * 2;
        const float2 bj = *(const float2*)(bias + col);
#pragma unroll
        for (int mt = 0; mt < 4; mt++) {
            const int row0 = bm + mt * 16 + gr;
            float2 v0, v1;
            v0.x = acc[mt][nt][0] + bj.x; v0.y = acc[mt][nt][1] + bj.y;
            v1.x = acc[mt][nt][2] + bj.x; v1.y = acc[mt][nt][3] + bj.y;
            *(float2*)(C + (size_t)row0 * N + col) = v0;
            *(float2*)(C + (size_t)(row0 + 8) * N + col) = v1;
        }
    }
}

// ---------------------------------------------------------------------------
// Flash attention (unchanged from R2 — FFMA-bound layout)
// ---------------------------------------------------------------------------
#define QT_STRIDE 68
#define KT_STRIDE 68
#define VS_STRIDE 96
#define PT_STRIDE 68
#define FLASH_SMEM_FLOATS (96*QT_STRIDE + 96*KT_STRIDE + 64*VS_STRIDE + 64*PT_STRIDE)
#define FLASH_SMEM_BYTES  (FLASH_SMEM_FLOATS * 4)

__global__ __launch_bounds__(128) void flash_attn(
    const float* __restrict__ qkv, float* __restrict__ out)
{
    extern __shared__ float sm[];
    float* Qt = sm;
    float* Kt = Qt + 96 * QT_STRIDE;
    float* Vs = Kt + 96 * KT_STRIDE;
    float* Pt = Vs + 64 * VS_STRIDE;

    const int qt = 15 - (int)blockIdx.x;
    const int h  = blockIdx.y;
    const int b  = blockIdx.z;
    const int tid = threadIdx.x;
    const int tq = tid >> 3;
    const int tk = tid & 7;

    const float rscale = 0.10206207261596577f;

    const float* qbase = qkv + (size_t)(b * T_SEQ + qt * 64) * 3 * C_EMB + h * HD;
    for (int i = tid; i < 64 * 24; i += 128) {
        int r = i / 24, c4 = (i % 24) * 4;
        float4 v = *(const float4*)(qbase + (size_t)r * 3 * C_EMB + c4);
        Qt[(c4 + 0) * QT_STRIDE + r] = v.x * rscale;
        Qt[(c4 + 1) * QT_STRIDE + r] = v.y * rscale;
        Qt[(c4 + 2) * QT_STRIDE + r] = v.z * rscale;
        Qt[(c4 + 3) * QT_STRIDE + r] = v.w * rscale;
    }

    float o[4][12];
#pragma unroll
    for (int i = 0; i < 4; i++)
#pragma unroll
        for (int d = 0; d < 12; d++) o[i][d] = 0.f;
    float m[4] = {-1e30f, -1e30f, -1e30f, -1e30f};
    float l[4] = {0.f, 0.f, 0.f, 0.f};

    for (int kt = 0; kt <= qt; kt++) {
        __syncthreads();
        const float* kbase = qkv + (size_t)(b * T_SEQ + kt * 64) * 3 * C_EMB + C_EMB + h * HD;
        const float* vbase = kbase + C_EMB;
        for (int i = tid; i < 64 * 24; i += 128) {
            int r = i / 24, c4 = (i % 24) * 4;
            float4 kv = *(const float4*)(kbase + (size_t)r * 3 * C_EMB + c4);
            float4 vv = *(const float4*)(vbase + (size_t)r * 3 * C_EMB + c4);
            Kt[(c4 + 0) * KT_STRIDE + r] = kv.x;
            Kt[(c4 + 1) * KT_STRIDE + r] = kv.y;
            Kt[(c4 + 2) * KT_STRIDE + r] = kv.z;
            Kt[(c4 + 3) * KT_STRIDE + r] = kv.w;
            *(float4*)&Vs[r * VS_STRIDE + c4] = vv;
        }
        __syncthreads();

        float s[4][8];
#pragma unroll
        for (int i = 0; i < 4; i++)
#pragma unroll
            for (int j = 0; j < 8; j++) s[i][j] = 0.f;

#pragma unroll 8
        for (int kk = 0; kk < HD; kk++) {
            float4 qv = *(const float4*)&Qt[kk * QT_STRIDE + 4 * tq];
            float4 k0 = *(const float4*)&Kt[kk * KT_STRIDE + 8 * tk];
            float4 k1 = *(const float4*)&Kt[kk * KT_STRIDE + 8 * tk + 4];
            float qa[4] = {qv.x, qv.y, qv.z, qv.w};
            float kb[8] = {k0.x, k0.y, k0.z, k0.w, k1.x, k1.y, k1.z, k1.w};
#pragma unroll
            for (int i = 0; i < 4; i++)
#pragma unroll
                for (int j = 0; j < 8; j++) s[i][j] += qa[i] * kb[j];
        }

        if (kt == qt) {
#pragma unroll
            for (int i = 0; i < 4; i++)
#pragma unroll
                for (int j = 0; j < 8; j++)
                    if (8 * tk + j > 4 * tq + i) s[i][j] = -1e30f;
        }

        float corr[4];
#pragma unroll
        for (int i = 0; i < 4; i++) {
            float mx = s[i][0];
#pragma unroll
            for (int j = 1; j < 8; j++) mx = fmaxf(mx, s[i][j]);
            mx = fmaxf(mx, __shfl_xor_sync(0xffffffffu, mx, 1));
            mx = fmaxf(mx, __shfl_xor_sync(0xffffffffu, mx, 2));
            mx = fmaxf(mx, __shfl_xor_sync(0xffffffffu, mx, 4));
            float mn = fmaxf(m[i], mx);
            corr[i] = __expf(m[i] - mn);
            m[i] = mn;
        }
        float rs[4];
#pragma unroll
        for (int i = 0; i < 4; i++) {
            rs[i] = 0.f;
#pragma unroll
            for (int j = 0; j < 8; j++) {
                s[i][j] = __expf(s[i][j] - m[i]);
                rs[i] += s[i][j];
            }
        }
#pragma unroll
        for (int j = 0; j < 8; j++) {
            float4 p;
            p.x = s[0][j]; p.y = s[1][j]; p.z = s[2][j]; p.w = s[3][j];
            *(float4*)&Pt[(8 * tk + j) * PT_STRIDE + 4 * tq] = p;
        }
#pragma unroll
        for (int i = 0; i < 4; i++) {
            rs[i] += __shfl_xor_sync(0xffffffffu, rs[i], 1);
            rs[i] += __shfl_xor_sync(0xffffffffu, rs[i], 2);
            rs[i] += __shfl_xor_sync(0xffffffffu, rs[i], 4);
            l[i] = l[i] * corr[i] + rs[i];
#pragma unroll
            for (int d = 0; d < 12; d++) o[i][d] *= corr[i];
        }
        __syncthreads();

#pragma unroll 4
        for (int k = 0; k < 64; k++) {
            float4 p = *(const float4*)&Pt[k * PT_STRIDE + 4 * tq];
            float pa[4] = {p.x, p.y, p.z, p.w};
            float4 v0 = *(const float4*)&Vs[k * VS_STRIDE + 12 * tk];
            float4 v1 = *(const float4*)&Vs[k * VS_STRIDE + 12 * tk + 4];
            float4 v2 = *(const float4*)&Vs[k * VS_STRIDE + 12 * tk + 8];
            float vb[12] = {v0.x, v0.y, v0.z, v0.w,
                            v1.x, v1.y, v1.z, v1.w,
                            v2.x, v2.y, v2.z, v2.w};
#pragma unroll
            for (int i = 0; i < 4; i++)
#pragma unroll
                for (int d = 0; d < 12; d++) o[i][d] += pa[i] * vb[d];
        }
    }

#pragma unroll
    for (int i = 0; i < 4; i++) {
        float inv_l = 1.f / l[i];
        float* ob = out + (size_t)(b * T_SEQ + qt * 64 + 4 * tq + i) * C_EMB
                        + h * HD + 12 * tk;
        float4 w0, w1, w2;
        w0.x = o[i][0] * inv_l;  w0.y = o[i][1] * inv_l;
        w0.z = o[i][2] * inv_l;  w0.w = o[i][3] * inv_l;
        w1.x = o[i][4] * inv_l;  w1.y = o[i][5] * inv_l;
        w1.z = o[i][6] * inv_l;  w1.w = o[i][7] * inv_l;
        w2.x = o[i][8] * inv_l;  w2.y = o[i][9] * inv_l;
        w2.z = o[i][10] * inv_l; w2.w = o[i][11] * inv_l;
        *(float4*)(ob + 0) = w0;
        *(float4*)(ob + 4) = w1;
        *(float4*)(ob + 8) = w2;
    }
}

// ---------------------------------------------------------------------------
// Launch
// ---------------------------------------------------------------------------
extern "C" void kernel_launch(void* const* d_in, const int* in_sizes, int n_in,
                              void* d_out, int out_size)
{
    (void)in_sizes; (void)n_in; (void)out_size;
    const float* x  = (const float*)d_in[0];
    const float* w1 = (const float*)d_in[1];
    const float* b1 = (const float*)d_in[2];
    const float* w2 = (const float*)d_in[3];
    const float* b2 = (const float*)d_in[4];
    float* out = (float*)d_out;

    float *qkv = nullptr, *att = nullptr;
    cudaGetSymbolAddress((void**)&qkv, g_qkv);
    cudaGetSymbolAddress((void**)&att, g_att);

    cudaFuncSetAttribute(gemm_mma,
                         cudaFuncAttributeMaxDynamicSharedMemorySize,
                         GEMM_SMEM_BYTES);
    cudaFuncSetAttribute(flash_attn,
                         cudaFuncAttributeMaxDynamicSharedMemorySize,
                         FLASH_SMEM_BYTES);

    // QKV projection: 8192 x 2304 x 768
    gemm_mma<<<dim3(3 * C_EMB / 128, M_ROWS / 64), 128, GEMM_SMEM_BYTES>>>(
        x, w1, b1, qkv, 3 * C_EMB);

    // Causal attention
    flash_attn<<<dim3(T_SEQ / 64, NH, BATCH), 128, FLASH_SMEM_BYTES>>>(qkv, att);

    // Output projection: 8192 x 768 x 768
    gemm_mma<<<dim3(C_EMB / 128, M_ROWS / 64), 128, GEMM_SMEM_BYTES>>>(
        att, w2, b2, out, C_EMB);
}

// round 6
// speedup vs baseline: 2.5472x; 2.5472x over previous
#include <cuda_runtime.h>
#include <cuda_bf16.h>
#include <math.h>
#include <stdint.h>

// Problem constants
#define BATCH 8
#define T_SEQ 1024
#define C_EMB 768
#define NH    8
#define HD    96
#define M_ROWS (BATCH * T_SEQ)   // 8192
#define GK    768

// ---------------------------------------------------------------------------
// Scratch
// ---------------------------------------------------------------------------
__device__ float g_qkv[(size_t)M_ROWS * 3 * C_EMB];
__device__ float g_att[(size_t)M_ROWS * C_EMB];

// ---------------------------------------------------------------------------
// mma.sync bf16 m16n8k16 (baseline PTX, ok at compute_103)
// ---------------------------------------------------------------------------
__device__ __forceinline__ void mma_bf16(
    float& c0, float& c1, float& c2, float& c3,
    uint32_t a0, uint32_t a1, uint32_t a2, uint32_t a3,
    uint32_t b0, uint32_t b1)
{
    asm volatile(
        "mma.sync.aligned.m16n8k16.row.col.f32.bf16.bf16.f32 "
        "{%0,%1,%2,%3}, {%4,%5,%6,%7}, {%8,%9}, {%0,%1,%2,%3};"
        : "+f"(c0), "+f"(c1), "+f"(c2), "+f"(c3)
        : "r"(a0), "r"(a1), "r"(a2), "r"(a3), "r"(b0), "r"(b1));
}

__device__ __forceinline__ uint32_t pkbf(__nv_bfloat16 a, __nv_bfloat16 b) {
    __nv_bfloat162 t(a, b);
    return *reinterpret_cast<uint32_t*>(&t);
}
__device__ __forceinline__ uint32_t pkf2(float a, float b) {
    __nv_bfloat162 t = __float22bfloat162_rn(make_float2(a, b));
    return *reinterpret_cast<uint32_t*>(&t);
}
// split pack: returns hi pair, writes lo pair
__device__ __forceinline__ uint32_t pksplit(float a, float b, uint32_t& lo) {
    __nv_bfloat16 ha = __float2bfloat16_rn(a);
    __nv_bfloat16 hb = __float2bfloat16_rn(b);
    lo = pkf2(a - __bfloat162float(ha), b - __bfloat162float(hb));
    return pkbf(ha, hb);
}

// ---------------------------------------------------------------------------
// Split-bf16 tensor-core GEMM (unchanged from R4 — passed at 1.16e-5)
// ---------------------------------------------------------------------------
#define AS_STRIDE 40
#define ABUF (64 * AS_STRIDE)
#define BBUF (128 * AS_STRIDE)
#define BUFSZ (2 * ABUF + 2 * BBUF)
#define GEMM_SMEM_BYTES (2 * BUFSZ * 2)
#define NCHUNK (GK / 32)

__global__ __launch_bounds__(128, 3) void gemm_mma(
    const float* __restrict__ A, const float* __restrict__ W,
    const float* __restrict__ bias, float* __restrict__ C, int N)
{
    extern __shared__ __nv_bfloat16 smb[];

    const int tid  = threadIdx.x;
    const int w    = tid >> 5;
    const int lane = tid & 31;
    const int gr   = lane >> 2;
    const int lc   = lane & 3;
    const int bm   = blockIdx.y * 64;
    const int bn   = blockIdx.x * 128;

    float acc[4][4][4];
#pragma unroll
    for (int mt = 0; mt < 4; mt++)
#pragma unroll
        for (int nt = 0; nt < 4; nt++)
#pragma unroll
            for (int r = 0; r < 4; r++) acc[mt][nt][r] = 0.f;

    {
        __nv_bfloat16* Ah = smb;
        __nv_bfloat16* Al = Ah + ABUF;
        __nv_bfloat16* Bh = Al + ABUF;
        __nv_bfloat16* Bl = Bh + BBUF;
#pragma unroll
        for (int j = 0; j < 4; j++) {
            int i = tid + 128 * j;
            int r = i >> 3, c4 = (i & 7) * 4;
            float4 v = *(const float4*)(A + (size_t)(bm + r) * GK + c4);
            uint32_t lx, ly;
            uint32_t hx = pksplit(v.x, v.y, lx);
            uint32_t hy = pksplit(v.z, v.w, ly);
            int idx = r * AS_STRIDE + c4;
            *(uint2*)&Ah[idx] = make_uint2(hx, hy);
            *(uint2*)&Al[idx] = make_uint2(lx, ly);
        }
#pragma unroll
        for (int j = 0; j < 8; j++) {
            int i = tid + 128 * j;
            int r = i >> 3, c4 = (i & 7) * 4;
            float4 v = *(const float4*)(W + (size_t)(bn + r) * GK + c4);
            uint32_t lx, ly;
            uint32_t hx = pksplit(v.x, v.y, lx);
            uint32_t hy = pksplit(v.z, v.w, ly);
            int idx = r * AS_STRIDE + c4;
            *(uint2*)&Bh[idx] = make_uint2(hx, hy);
            *(uint2*)&Bl[idx] = make_uint2(lx, ly);
        }
    }
    __syncthreads();

    float4 pa[4], pb[8];
    for (int t = 0; t < NCHUNK; t++) {
        const bool more = (t + 1) < NCHUNK;
        if (more) {
            const int k0 = (t + 1) * 32;
#pragma unroll
            for (int j = 0; j < 4; j++) {
                int i = tid + 128 * j;
                int r = i >> 3, c4 = (i & 7) * 4;
                pa[j] = *(const float4*)(A + (size_t)(bm + r) * GK + k0 + c4);
            }
#pragma unroll
            for (int j = 0; j < 8; j++) {
                int i = tid + 128 * j;
                int r = i >> 3, c4 = (i & 7) * 4;
                pb[j] = *(const float4*)(W + (size_t)(bn + r) * GK + k0 + c4);
            }
        }

        {
            __nv_bfloat16* buf = smb + (t & 1) * BUFSZ;
            __nv_bfloat16* Ah = buf;
            __nv_bfloat16* Al = Ah + ABUF;
            __nv_bfloat16* Bh = Al + ABUF;
            __nv_bfloat16* Bl = Bh + BBUF;

#pragma unroll
            for (int ks = 0; ks < 2; ks++) {
                const int kb = ks * 16;
                uint32_t af[4][4], bhf[4][2], blf[4][2];
#pragma unroll
                for (int mt = 0; mt < 4; mt++) {
                    int r0 = (mt * 16 + gr) * AS_STRIDE + kb + lc * 2;
                    int r1 = r0 + 8 * AS_STRIDE;
                    af[mt][0] = *(const uint32_t*)&Ah[r0];
                    af[mt][1] = *(const uint32_t*)&Ah[r1];
                    af[mt][2] = *(const uint32_t*)&Ah[r0 + 8];
                    af[mt][3] = *(const uint32_t*)&Ah[r1 + 8];
                }
#pragma unroll
                for (int nt = 0; nt < 4; nt++) {
                    int rb = (w * 32 + nt * 8 + gr) * AS_STRIDE + kb + lc * 2;
                    bhf[nt][0] = *(const uint32_t*)&Bh[rb];
                    bhf[nt][1] = *(const uint32_t*)&Bh[rb + 8];
                    blf[nt][0] = *(const uint32_t*)&Bl[rb];
                    blf[nt][1] = *(const uint32_t*)&Bl[rb + 8];
                }
#pragma unroll
                for (int mt = 0; mt < 4; mt++)
#pragma unroll
                    for (int nt = 0; nt < 4; nt++) {
                        mma_bf16(acc[mt][nt][0], acc[mt][nt][1],
                                 acc[mt][nt][2], acc[mt][nt][3],
                                 af[mt][0], af[mt][1], af[mt][2], af[mt][3],
                                 bhf[nt][0], bhf[nt][1]);
                        mma_bf16(acc[mt][nt][0], acc[mt][nt][1],
                                 acc[mt][nt][2], acc[mt][nt][3],
                                 af[mt][0], af[mt][1], af[mt][2], af[mt][3],
                                 blf[nt][0], blf[nt][1]);
                    }
#pragma unroll
                for (int mt = 0; mt < 4; mt++) {
                    int r0 = (mt * 16 + gr) * AS_STRIDE + kb + lc * 2;
                    int r1 = r0 + 8 * AS_STRIDE;
                    af[mt][0] = *(const uint32_t*)&Al[r0];
                    af[mt][1] = *(const uint32_t*)&Al[r1];
                    af[mt][2] = *(const uint32_t*)&Al[r0 + 8];
                    af[mt][3] = *(const uint32_t*)&Al[r1 + 8];
                }
#pragma unroll
                for (int mt = 0; mt < 4; mt++)
#pragma unroll
                    for (int nt = 0; nt < 4; nt++)
                        mma_bf16(acc[mt][nt][0], acc[mt][nt][1],
                                 acc[mt][nt][2], acc[mt][nt][3],
                                 af[mt][0], af[mt][1], af[mt][2], af[mt][3],
                                 bhf[nt][0], bhf[nt][1]);
            }
        }

        if (more) {
            __nv_bfloat16* buf = smb + ((t + 1) & 1) * BUFSZ;
            __nv_bfloat16* Ah = buf;
            __nv_bfloat16* Al = Ah + ABUF;
            __nv_bfloat16* Bh = Al + ABUF;
            __nv_bfloat16* Bl = Bh + BBUF;
#pragma unroll
            for (int j = 0; j < 4; j++) {
                int i = tid + 128 * j;
                int r = i >> 3, c4 = (i & 7) * 4;
                float4 v = pa[j];
                uint32_t lx, ly;
                uint32_t hx = pksplit(v.x, v.y, lx);
                uint32_t hy = pksplit(v.z, v.w, ly);
                int idx = r * AS_STRIDE + c4;
                *(uint2*)&Ah[idx] = make_uint2(hx, hy);
                *(uint2*)&Al[idx] = make_uint2(lx, ly);
            }
#pragma unroll
            for (int j = 0; j < 8; j++) {
                int i = tid + 128 * j;
                int r = i >> 3, c4 = (i & 7) * 4;
                float4 v = pb[j];
                uint32_t lx, ly;
                uint32_t hx = pksplit(v.x, v.y, lx);
                uint32_t hy = pksplit(v.z, v.w, ly);
                int idx = r * AS_STRIDE + c4;
                *(uint2*)&Bh[idx] = make_uint2(hx, hy);
                *(uint2*)&Bl[idx] = make_uint2(lx, ly);
            }
        }
        __syncthreads();
    }

#pragma unroll
    for (int nt = 0; nt < 4; nt++) {
        const int col = bn + w * 32 + nt * 8 + lc * 2;
        const float2 bj = *(const float2*)(bias + col);
#pragma unroll
        for (int mt = 0; mt < 4; mt++) {
            const int row0 = bm + mt * 16 + gr;
            float2 v0, v1;
            v0.x = acc[mt][nt][0] + bj.x; v0.y = acc[mt][nt][1] + bj.y;
            v1.x = acc[mt][nt][2] + bj.x; v1.y = acc[mt][nt][3] + bj.y;
            *(float2*)(C + (size_t)row0 * N + col) = v0;
            *(float2*)(C + (size_t)(row0 + 8) * N + col) = v1;
        }
    }
}

// ---------------------------------------------------------------------------
// Flash attention on mma.sync, split-bf16 on BOTH QK^T and PV.
// Block = (64 q-rows, head, batch); 128 threads = 4 warps x 16 q-rows.
// QK^T: Qh*Kh + Qh*Kl + Ql*Kh.  PV: Ph*Vh + Ph*Vl + Pl*Vh.
// V transposed in smem ([d][tok]) split hi/lo.
// ---------------------------------------------------------------------------
#define KST 104           // K smem row stride (bf16)
#define VST 72            // Vt smem row stride (bf16)
#define FL_KL_OFF (64 * KST)
#define FL_VT_OFF (2 * 64 * KST)
#define FL_VTL_OFF (FL_VT_OFF + 96 * VST)
#define FL_SMEM_BF16 (2 * 64 * KST + 2 * 96 * VST)
#define FL_SMEM_BYTES (FL_SMEM_BF16 * 2)   // 54272

__global__ __launch_bounds__(128, 2) void flash_mma(
    const float* __restrict__ qkv, float* __restrict__ out)
{
    extern __shared__ char fsm[];
    __nv_bfloat16* Kh  = (__nv_bfloat16*)fsm;
    __nv_bfloat16* Kl  = Kh + FL_KL_OFF;
    __nv_bfloat16* Vth = Kh + FL_VT_OFF;
    __nv_bfloat16* Vtl = Kh + FL_VTL_OFF;
    float* Qs = (float*)fsm;               // overlays K region, pre-loop only

    const int qt = 15 - (int)blockIdx.x;
    const int h  = blockIdx.y;
    const int b  = blockIdx.z;
    const int tid  = threadIdx.x;
    const int w    = tid >> 5;
    const int lane = tid & 31;
    const int gr   = lane >> 2;
    const int lc   = lane & 3;
    const int r0l  = w * 16 + gr;
    const int r1l  = r0l + 8;

    const float rscale = 0.10206207261596577f;  // 1/sqrt(96)

    // ---- stage Q (scaled) into smem, then extract per-thread A-fragments ----
    const float* qbase = qkv + (size_t)(b * T_SEQ + qt * 64) * 3 * C_EMB + h * HD;
#pragma unroll
    for (int it = 0; it < 12; it++) {
        int idx = tid + 128 * it;
        int r = idx / 24, c4 = (idx % 24) * 4;
        float4 v = *(const float4*)(qbase + (size_t)r * 3 * C_EMB + c4);
        v.x *= rscale; v.y *= rscale; v.z *= rscale; v.w *= rscale;
        *(float4*)&Qs[r * 100 + c4] = v;
    }
    __syncthreads();

    uint32_t Qhf[6][4], Qlf[6][4];
#pragma unroll
    for (int ks = 0; ks < 6; ks++) {
        const int kb = ks * 16 + 2 * lc;
#pragma unroll
        for (int f = 0; f < 4; f++) {
            const int rr = (f & 1) ? r1l : r0l;
            const int kk = kb + ((f >> 1) ? 8 : 0);
            Qhf[ks][f] = pksplit(Qs[rr * 100 + kk], Qs[rr * 100 + kk + 1], Qlf[ks][f]);
        }
    }
    __syncthreads();

    float accO[12][4];
#pragma unroll
    for (int nt = 0; nt < 12; nt++)
#pragma unroll
        for (int r = 0; r < 4; r++) accO[nt][r] = 0.f;
    float m0 = -1e30f, m1 = -1e30f, l0 = 0.f, l1 = 0.f;

    for (int kt = 0; kt <= qt; kt++) {
        const float* kb_ = qkv + (size_t)(b * T_SEQ + kt * 64) * 3 * C_EMB + C_EMB + h * HD;
        const float* vb_ = kb_ + C_EMB;

        // K tile split hi/lo, K-major rows
#pragma unroll
        for (int it = 0; it < 12; it++) {
            int idx = tid + 128 * it;
            int r = idx / 24, c4 = (idx % 24) * 4;
            float4 v = *(const float4*)(kb_ + (size_t)r * 3 * C_EMB + c4);
            uint32_t lx, ly;
            uint32_t hx = pksplit(v.x, v.y, lx);
            uint32_t hy = pksplit(v.z, v.w, ly);
            int sidx = r * KST + c4;
            *(uint2*)&Kh[sidx] = make_uint2(hx, hy);
            *(uint2*)&Kl[sidx] = make_uint2(lx, ly);
        }
        // V tile transposed [d][tok], split hi/lo, packed token-pairs
#pragma unroll
        for (int it = 0; it < 6; it++) {
            int idx = tid + 128 * it;
            int t2 = idx & 31, d4 = (idx >> 5) * 4;
            float4 v0 = *(const float4*)(vb_ + (size_t)(2 * t2) * 3 * C_EMB + d4);
            float4 v1 = *(const float4*)(vb_ + (size_t)(2 * t2 + 1) * 3 * C_EMB + d4);
            uint32_t lo;
#pragma unroll
            for (int c = 0; c < 4; c++) {
                float a = (&v0.x)[c], bb = (&v1.x)[c];
                uint32_t hi = pksplit(a, bb, lo);
                *(uint32_t*)&Vth[(d4 + c) * VST + 2 * t2] = hi;
                *(uint32_t*)&Vtl[(d4 + c) * VST + 2 * t2] = lo;
            }
        }
        __syncthreads();

        // ---- S = Q K^T (3-product split) ----
        float accS[8][4];
#pragma unroll
        for (int nt = 0; nt < 8; nt++)
#pragma unroll
            for (int r = 0; r < 4; r++) accS[nt][r] = 0.f;

#pragma unroll
        for (int ks = 0; ks < 6; ks++) {
            const int kx = ks * 16 + 2 * lc;
            uint32_t bh[8][2], bl[8][2];
#pragma unroll
            for (int nt = 0; nt < 8; nt++) {
                int rb = (nt * 8 + gr) * KST + kx;
                bh[nt][0] = *(const uint32_t*)&Kh[rb];
                bh[nt][1] = *(const uint32_t*)&Kh[rb + 8];
                bl[nt][0] = *(const uint32_t*)&Kl[rb];
                bl[nt][1] = *(const uint32_t*)&Kl[rb + 8];
            }
#pragma unroll
            for (int nt = 0; nt < 8; nt++) {
                mma_bf16(accS[nt][0], accS[nt][1], accS[nt][2], accS[nt][3],
                         Qhf[ks][0], Qhf[ks][1], Qhf[ks][2], Qhf[ks][3],
                         bh[nt][0], bh[nt][1]);
                mma_bf16(accS[nt][0], accS[nt][1], accS[nt][2], accS[nt][3],
                         Qhf[ks][0], Qhf[ks][1], Qhf[ks][2], Qhf[ks][3],
                         bl[nt][0], bl[nt][1]);
                mma_bf16(accS[nt][0], accS[nt][1], accS[nt][2], accS[nt][3],
                         Qlf[ks][0], Qlf[ks][1], Qlf[ks][2], Qlf[ks][3],
                         bh[nt][0], bh[nt][1]);
            }
        }

        // ---- causal mask on diagonal tile ----
        if (kt == qt) {
#pragma unroll
            for (int nt = 0; nt < 8; nt++) {
                int c0 = nt * 8 + 2 * lc, c1 = c0 + 1;
                if (c0 > r0l) accS[nt][0] = -1e30f;
                if (c1 > r0l) accS[nt][1] = -1e30f;
                if (c0 > r1l) accS[nt][2] = -1e30f;
                if (c1 > r1l) accS[nt][3] = -1e30f;
            }
        }

        // ---- online softmax ----
        float mx0 = accS[0][0], mx1 = accS[0][2];
#pragma unroll
        for (int nt = 0; nt < 8; nt++) {
            mx0 = fmaxf(mx0, fmaxf(accS[nt][0], accS[nt][1]));
            mx1 = fmaxf(mx1, fmaxf(accS[nt][2], accS[nt][3]));
        }
        mx0 = fmaxf(mx0, __shfl_xor_sync(0xffffffffu, mx0, 1));
        mx0 = fmaxf(mx0, __shfl_xor_sync(0xffffffffu, mx0, 2));
        mx1 = fmaxf(mx1, __shfl_xor_sync(0xffffffffu, mx1, 1));
        mx1 = fmaxf(mx1, __shfl_xor_sync(0xffffffffu, mx1, 2));
        float nm0 = fmaxf(m0, mx0), nm1 = fmaxf(m1, mx1);
        float corr0 = __expf(m0 - nm0), corr1 = __expf(m1 - nm1);
        m0 = nm0; m1 = nm1;

        float rs0 = 0.f, rs1 = 0.f;
        uint32_t aPh[4][4], aPl[4][4];
#pragma unroll
        for (int nt = 0; nt < 8; nt++) {
            float p0 = __expf(accS[nt][0] - m0);
            float p1 = __expf(accS[nt][1] - m0);
            float p2 = __expf(accS[nt][2] - m1);
            float p3 = __expf(accS[nt][3] - m1);
            rs0 += p0 + p1; rs1 += p2 + p3;
            const int i0 = (nt & 1) * 2;
            aPh[nt >> 1][i0 + 0] = pksplit(p0, p1, aPl[nt >> 1][i0 + 0]);
            aPh[nt >> 1][i0 + 1] = pksplit(p2, p3, aPl[nt >> 1][i0 + 1]);
        }
        rs0 += __shfl_xor_sync(0xffffffffu, rs0, 1);
        rs0 += __shfl_xor_sync(0xffffffffu, rs0, 2);
        rs1 += __shfl_xor_sync(0xffffffffu, rs1, 1);
        rs1 += __shfl_xor_sync(0xffffffffu, rs1, 2);
        l0 = l0 * corr0 + rs0;
        l1 = l1 * corr1 + rs1;

#pragma unroll
        for (int nt = 0; nt < 12; nt++) {
            accO[nt][0] *= corr0; accO[nt][1] *= corr0;
            accO[nt][2] *= corr1; accO[nt][3] *= corr1;
        }

        // ---- O += P V (3-product split) ----
#pragma unroll
        for (int kt2 = 0; kt2 < 4; kt2++) {
            const int kx2 = kt2 * 16 + 2 * lc;
            uint32_t a0 = aPh[kt2][0], a1 = aPh[kt2][1], a2 = aPh[kt2][2], a3 = aPh[kt2][3];
            uint32_t c0 = aPl[kt2][0], c1 = aPl[kt2][1], c2 = aPl[kt2][2], c3 = aPl[kt2][3];
#pragma unroll
            for (int nt = 0; nt < 12; nt++) {
                int rb = (nt * 8 + gr) * VST + kx2;
                uint32_t b0h = *(const uint32_t*)&Vth[rb];
                uint32_t b1h = *(const uint32_t*)&Vth[rb + 8];
                uint32_t b0l = *(const uint32_t*)&Vtl[rb];
                uint32_t b1l = *(const uint32_t*)&Vtl[rb + 8];
                mma_bf16(accO[nt][0], accO[nt][1], accO[nt][2], accO[nt][3],
                         a0, a1, a2, a3, b0h, b1h);
                mma_bf16(accO[nt][0], accO[nt][1], accO[nt][2], accO[nt][3],
                         a0, a1, a2, a3, b0l, b1l);
                mma_bf16(accO[nt][0], accO[nt][1], accO[nt][2], accO[nt][3],
                         c0, c1, c2, c3, b0h, b1h);
            }
        }
        __syncthreads();
    }

    // ---- epilogue ----
    const float inv0 = 1.f / l0;
    const float inv1 = 1.f / l1;
    const size_t grow0 = (size_t)(b * T_SEQ + qt * 64 + r0l);
    const size_t grow1 = grow0 + 8;
#pragma unroll
    for (int nt = 0; nt < 12; nt++) {
        const int col = h * HD + nt * 8 + 2 * lc;
        float2 v0, v1;
        v0.x = accO[nt][0] * inv0; v0.y = accO[nt][1] * inv0;
        v1.x = accO[nt][2] * inv1; v1.y = accO[nt][3] * inv1;
        *(float2*)(out + grow0 * C_EMB + col) = v0;
        *(float2*)(out + grow1 * C_EMB + col) = v1;
    }
}

// ---------------------------------------------------------------------------
// Launch
// ---------------------------------------------------------------------------
extern "C" void kernel_launch(void* const* d_in, const int* in_sizes, int n_in,
                              void* d_out, int out_size)
{
    (void)in_sizes; (void)n_in; (void)out_size;
    const float* x  = (const float*)d_in[0];
    const float* w1 = (const float*)d_in[1];
    const float* b1 = (const float*)d_in[2];
    const float* w2 = (const float*)d_in[3];
    const float* b2 = (const float*)d_in[4];
    float* out = (float*)d_out;

    float *qkv = nullptr, *att = nullptr;
    cudaGetSymbolAddress((void**)&qkv, g_qkv);
    cudaGetSymbolAddress((void**)&att, g_att);

    cudaFuncSetAttribute(gemm_mma,
                         cudaFuncAttributeMaxDynamicSharedMemorySize,
                         GEMM_SMEM_BYTES);
    cudaFuncSetAttribute(flash_mma,
                         cudaFuncAttributeMaxDynamicSharedMemorySize,
                         FL_SMEM_BYTES);

    // QKV projection: 8192 x 2304 x 768
    gemm_mma<<<dim3(3 * C_EMB / 128, M_ROWS / 64), 128, GEMM_SMEM_BYTES>>>(
        x, w1, b1, qkv, 3 * C_EMB);

    // Causal attention (tensor-core flash, split-bf16 both phases)
    flash_mma<<<dim3(T_SEQ / 64, NH, BATCH), 128, FL_SMEM_BYTES>>>(qkv, att);

    // Output projection: 8192 x 768 x 768
    gemm_mma<<<dim3(C_EMB / 128, M_ROWS / 64), 128, GEMM_SMEM_BYTES>>>(
        att, w2, b2, out, C_EMB);
}